// round 12
// baseline (speedup 1.0000x reference)
#include <cuda_runtime.h>
#include <cuda_fp16.h>
#include <math.h>
#include <stdint.h>

#define BSZ   32
#define LQ    512
#define DM    768
#define NHID  192
#define KC    5
#define DI    1536
#define DS    16
#define DTR   48
#define DXP   (DTR+2*DS)      // 112
#define DCONV 4
#define ML    (BSZ*LQ)        // 16384 rows
#define EPSV  1e-5f
#define BNCH  32

// fp16-mma GEMM tiling: CTA 128x128, K-chunk 32 halfs, 8 warps 4x2
#define TGK     32
#define PITCHW  20
#define TILEW   (128*PITCHW)
#define TG_SMEMB (4*TILEW*4)            // 40960 bytes

// weight scratch offsets (halfs) — gate right after in_proj for merged GEMM
#define OFF_SQ  0
#define OFF_EX  147456
#define OFF_INP 294912
#define OFF_GW  2654208
#define OFF_XP  3244032
#define OFF_DT  3416064
#define OFF_OP  3489792
#define WH_TOT  4669440

// ---------------- scratch buffers ----------------
__device__ __half g_wh [WH_TOT];
__device__ __half g_h  [ML*NHID];
__device__ __half g_h2 [ML*NHID];
__device__ __half g_xnh[ML*DM];
__device__ __half g_xm [(size_t)ML*DI];
__device__ __half g_z  [(size_t)ML*DI];
__device__ __half g_xmc[(size_t)ML*DI];
__device__ __half g_dbc[ML*DXP];
__device__ __half g_del[(size_t)ML*DI];
__device__ __half g_y  [(size_t)ML*DI];
__device__ __half g_mo [ML*DM];
__device__ __half g_gt [ML*DM];
__device__ float  g_x1 [ML*DM];
__device__ float  g_xf [ML*DM];
__device__ float  g_rm [ML];
__device__ float  g_rs [ML];
__device__ float  g_cm [4096];
__device__ float  g_cs [4096];
__device__ float  g_ps [BNCH*1024];
__device__ float  g_pq [BNCH*1024];

// ===================== helpers =============================================
__device__ __forceinline__ void mma_f16(float* d, const uint32_t* a, const uint32_t* b) {
    asm volatile(
        "mma.sync.aligned.m16n8k16.row.col.f32.f16.f16.f32 "
        "{%0,%1,%2,%3}, {%4,%5,%6,%7}, {%8,%9}, {%0,%1,%2,%3};"
        : "+f"(d[0]), "+f"(d[1]), "+f"(d[2]), "+f"(d[3])
        : "r"(a[0]), "r"(a[1]), "r"(a[2]), "r"(a[3]), "r"(b[0]), "r"(b[1]));
}
__device__ __forceinline__ void ldsm_x4(uint32_t& r0, uint32_t& r1, uint32_t& r2,
                                        uint32_t& r3, uint32_t addr) {
    asm volatile("ldmatrix.sync.aligned.m8n8.x4.shared.b16 {%0,%1,%2,%3}, [%4];"
                 : "=r"(r0), "=r"(r1), "=r"(r2), "=r"(r3) : "r"(addr));
}
__device__ __forceinline__ float fsilu(float v)   { return __fdividef(v, 1.f + __expf(-v)); }
__device__ __forceinline__ float fsigm(float v)   { return __fdividef(1.f, 1.f + __expf(-v)); }

// ---------------- converts -------------------------------------------------
__global__ void f2h4(const float* __restrict__ src, __half* __restrict__ dst, long n)
{
    long i = ((long)blockIdx.x * blockDim.x + threadIdx.x) * 4;
    if (i >= n) return;
    float4 v = *(const float4*)(src + i);
    __half2 a = __floats2half2_rn(v.x, v.y);
    __half2 b = __floats2half2_rn(v.z, v.w);
    *(__half2*)(dst + i) = a;
    *(__half2*)(dst + i + 2) = b;
}
__global__ void wconv(const float* __restrict__ s0, const float* __restrict__ s1,
                      const float* __restrict__ s2, const float* __restrict__ s3,
                      const float* __restrict__ s4, const float* __restrict__ s5,
                      const float* __restrict__ s6, __half* __restrict__ dst)
{
    long i = ((long)blockIdx.x * blockDim.x + threadIdx.x) * 4;
    if (i >= WH_TOT) return;
    const float* src; long off;
    if      (i < OFF_EX)  { src = s0; off = i - OFF_SQ;  }
    else if (i < OFF_INP) { src = s1; off = i - OFF_EX;  }
    else if (i < OFF_GW)  { src = s2; off = i - OFF_INP; }
    else if (i < OFF_XP)  { src = s3; off = i - OFF_GW;  }
    else if (i < OFF_DT)  { src = s4; off = i - OFF_XP;  }
    else if (i < OFF_OP)  { src = s5; off = i - OFF_DT;  }
    else                  { src = s6; off = i - OFF_OP;  }
    float4 v = *(const float4*)(src + off);
    *(__half2*)(dst + i)     = __floats2half2_rn(v.x, v.y);
    *(__half2*)(dst + i + 2) = __floats2half2_rn(v.z, v.w);
}

// ===================== fp16 tensor GEMM (ldmatrix, 3-way split) ============
__global__ void __launch_bounds__(256, 2)
tgemm(const __half* __restrict__ A, int lda,
      const __half* __restrict__ W, int ldw,
      const float* __restrict__ bias,
      __half* __restrict__ C, int ldc,
      __half* __restrict__ C2, int ldc2, int splitN,
      __half* __restrict__ C3, int ldc3, int splitN2, const float* __restrict__ bias3,
      int M, int N, int K, int act)
{
    extern __shared__ uint32_t smem[];
    const int tid = threadIdx.x;
    const int wid = tid >> 5, lane = tid & 31;
    const int g = lane >> 2, t = lane & 3;
    const int wm = wid & 3, wn = wid >> 2;
    const int row0 = blockIdx.y * 128, col0 = blockIdx.x * 128;
    const uint32_t smem_b = (uint32_t)__cvta_generic_to_shared(smem);

    const int a_row = lane & 15;
    const int a_kw  = (lane >> 4) * 4;
    const int b_row = (lane & 7) + ((lane >> 4) << 3);
    const int b_kw  = ((lane >> 3) & 1) * 4;

    float acc[2][8][4];
#pragma unroll
    for (int mt = 0; mt < 2; mt++)
#pragma unroll
        for (int nt = 0; nt < 8; nt++)
#pragma unroll
            for (int j = 0; j < 4; j++) acc[mt][nt][j] = 0.f;

    const int nch = (K + TGK - 1) / TGK;

    uint4 pa[2], pb[2];
    auto ldg_chunk = [&](int ch) {
        const int k0 = ch * TGK;
#pragma unroll
        for (int i = 0; i < 2; i++) {
            int e = tid + i * 256;
            int r = e >> 2, q = e & 3;
            int gk = k0 + q * 8;
            pa[i] = make_uint4(0, 0, 0, 0);
            pb[i] = make_uint4(0, 0, 0, 0);
            if (gk < K) {
                pa[i] = *(const uint4*)(A + (long)(row0 + r) * lda + gk);
                int n = col0 + r;
                if (n < N) pb[i] = *(const uint4*)(W + (long)n * ldw + gk);
            }
        }
    };
    auto sts_chunk = [&](int buf) {
        uint32_t* As = smem + buf * 2 * TILEW;
        uint32_t* Bs = As + TILEW;
#pragma unroll
        for (int i = 0; i < 2; i++) {
            int e = tid + i * 256;
            int r = e >> 2, q = e & 3;
            int o = r * PITCHW + q * 4;
            *(uint4*)(As + o) = pa[i];
            *(uint4*)(Bs + o) = pb[i];
        }
    };
    auto compute_chunk = [&](int buf) {
        const uint32_t Ab = smem_b + (uint32_t)(buf * 2 * TILEW) * 4;
        const uint32_t Bb = Ab + TILEW * 4;
#pragma unroll
        for (int ks = 0; ks < 2; ks++) {
            const int kw = ks * 8;
            uint32_t af[2][4], bf[8][2];
#pragma unroll
            for (int mt = 0; mt < 2; mt++) {
                uint32_t addr = Ab + (uint32_t)(((wm * 32 + mt * 16 + a_row) * PITCHW
                                                + kw + a_kw) * 4);
                ldsm_x4(af[mt][0], af[mt][1], af[mt][2], af[mt][3], addr);
            }
#pragma unroll
            for (int j = 0; j < 4; j++) {
                uint32_t addr = Bb + (uint32_t)(((wn * 64 + j * 16 + b_row) * PITCHW
                                                + kw + b_kw) * 4);
                ldsm_x4(bf[2 * j][0], bf[2 * j][1], bf[2 * j + 1][0], bf[2 * j + 1][1], addr);
            }
#pragma unroll
            for (int mt = 0; mt < 2; mt++)
#pragma unroll
                for (int nt = 0; nt < 8; nt++)
                    mma_f16(acc[mt][nt], af[mt], bf[nt]);
        }
    };

    ldg_chunk(0);
    sts_chunk(0);
    __syncthreads();
    for (int ch = 1; ch < nch; ch++) {
        ldg_chunk(ch);
        compute_chunk((ch - 1) & 1);
        sts_chunk(ch & 1);
        __syncthreads();
    }
    compute_chunk((nch - 1) & 1);

    // ---- epilogue: 3-way column split; C3 region forces sigmoid+bias3 ----
    __half* Cp = C; int cof = col0, ldco = ldc;
    int actL = act; const float* bL = bias; int boff = 0;
    if (C3 && col0 >= splitN2) {
        Cp = C3; cof = col0 - splitN2; ldco = ldc3; actL = 3; bL = bias3; boff = splitN2;
    } else if (C2 && col0 >= splitN) {
        Cp = C2; cof = col0 - splitN; ldco = ldc2;
    }
#pragma unroll
    for (int mt = 0; mt < 2; mt++) {
        int r0 = row0 + wm * 32 + mt * 16 + g;
#pragma unroll
        for (int nt = 0; nt < 8; nt++) {
            int c0 = cof + wn * 64 + nt * 8 + t * 2;
            int cg = col0 + wn * 64 + nt * 8 + t * 2;
            if (cg >= N) continue;
#pragma unroll
            for (int half_ = 0; half_ < 2; half_++) {
                int r = r0 + half_ * 8;
                float v0 = acc[mt][nt][half_ * 2 + 0];
                float v1 = acc[mt][nt][half_ * 2 + 1];
                if (bL) { v0 += bL[cg - boff]; v1 += bL[cg - boff + 1]; }
                if (actL == 2) {
                    v0 = (v0 > 20.f) ? v0 : log1pf(__expf(v0));
                    v1 = (v1 > 20.f) ? v1 : log1pf(__expf(v1));
                } else if (actL == 3) {
                    v0 = fsigm(v0);
                    v1 = fsigm(v1);
                }
                *(__half2*)(Cp + (long)r * ldco + c0) = __floats2half2_rn(v0, v1);
            }
        }
    }
}

// ===================== two-phase BN stats ==================================
__global__ void bn_part(const __half* __restrict__ src, int M, int N,
                        float* __restrict__ ps, float* __restrict__ pq)
{
    int c = blockIdx.x * 32 + threadIdx.x;
    int ch = blockIdx.y;
    int rows = M / BNCH;
    int r0 = ch * rows;
    float s = 0.f, sq = 0.f;
    if (c < N) {
        for (int r = r0 + threadIdx.y; r < r0 + rows; r += blockDim.y) {
            float v = __half2float(src[(long)r * N + c]);
            s += v; sq += v * v;
        }
    }
    __shared__ float sh[32][33], sh2[32][33];
    sh[threadIdx.y][threadIdx.x] = s;
    sh2[threadIdx.y][threadIdx.x] = sq;
    __syncthreads();
    if (threadIdx.y == 0 && c < N) {
#pragma unroll
        for (int i = 1; i < 32; i++) { s += sh[i][threadIdx.x]; sq += sh2[i][threadIdx.x]; }
        ps[ch * N + c] = s;
        pq[ch * N + c] = sq;
    }
}
__global__ void bn_final(const float* __restrict__ ps, const float* __restrict__ pq,
                         int M, int N, float* __restrict__ mean, float* __restrict__ rstd)
{
    int c = blockIdx.x * blockDim.x + threadIdx.x;
    if (c >= N) return;
    float s = 0.f, sq = 0.f;
#pragma unroll
    for (int ch = 0; ch < BNCH; ch++) { s += ps[ch * N + c]; sq += pq[ch * N + c]; }
    float m = s / (float)M;
    mean[c] = m;
    rstd[c] = rsqrtf(fmaxf(sq / (float)M - m * m, 0.f) + EPSV);
}

// BN apply + silu, 2 elements/thread
__global__ void bn_apply_h2(const __half* __restrict__ src, __half* __restrict__ dst,
                            const float* __restrict__ mean, const float* __restrict__ rstd,
                            const float* __restrict__ g, const float* __restrict__ b,
                            long total2, int N)
{
    long i2 = (long)blockIdx.x * blockDim.x + threadIdx.x;
    if (i2 >= total2) return;
    long i = i2 * 2;
    int c = (int)(i % N);
    __half2 hv = *(const __half2*)(src + i);
    float2 f = __half22float2(hv);
    float v0 = (f.x - mean[c]) * rstd[c] * g[c] + b[c];
    float v1 = (f.y - mean[c + 1]) * rstd[c + 1] * g[c + 1] + b[c + 1];
    *(__half2*)(dst + i) = __floats2half2_rn(fsilu(v0), fsilu(v1));
}

// depthwise conv5, 2 channels/thread
__global__ void dwconv5_h2(const __half* __restrict__ src, const float* __restrict__ w,
                           __half* __restrict__ dst)
{
    long i2 = (long)blockIdx.x * blockDim.x + threadIdx.x;
    if (i2 >= (long)ML * NHID / 2) return;
    int c2 = (int)(i2 % (NHID / 2));
    int c = c2 * 2;
    long bl = i2 / (NHID / 2);
    int l = (int)(bl % LQ);
    long b = bl / LQ;
    float a0 = 0.f, a1 = 0.f;
#pragma unroll
    for (int k = 0; k < KC; k++) {
        int ll = l + k - 2;
        if (ll >= 0 && ll < LQ) {
            float2 f = __half22float2(*(const __half2*)(src + (b * LQ + ll) * NHID + c));
            a0 += f.x * w[c * KC + k];
            a1 += f.y * w[(c + 1) * KC + k];
        }
    }
    *(__half2*)(dst + bl * NHID + c) = __floats2half2_rn(a0, a1);
}

// causal conv4 + bias + silu, 2 channels/thread
__global__ void cconv4_h2(const __half* __restrict__ xm, const float* __restrict__ w,
                          const float* __restrict__ cb, __half* __restrict__ dst)
{
    long i2 = (long)blockIdx.x * blockDim.x + threadIdx.x;
    if (i2 >= (long)ML * DI / 2) return;
    int c2 = (int)(i2 % (DI / 2));
    int c = c2 * 2;
    long bl = i2 / (DI / 2);
    int l = (int)(bl % LQ);
    long b = bl / LQ;
    float a0 = cb[c], a1 = cb[c + 1];
#pragma unroll
    for (int k = 0; k < DCONV; k++) {
        int ll = l + k - (DCONV - 1);
        if (ll >= 0) {
            float2 f = __half22float2(*(const __half2*)(xm + (b * LQ + ll) * (long)DI + c));
            a0 += f.x * w[c * DCONV + k];
            a1 += f.y * w[(c + 1) * DCONV + k];
        }
    }
    *(__half2*)(dst + bl * (long)DI + c) = __floats2half2_rn(fsilu(a0), fsilu(a1));
}

// fused BN(ex)+residual -> x1 ; LN stats ; LN apply -> xn (half)
__global__ void bnx1_ln(const __half* __restrict__ mo, const float* __restrict__ x,
                        const float* __restrict__ cm, const float* __restrict__ cs,
                        const float* __restrict__ exg, const float* __restrict__ exb,
                        const float* __restrict__ mg, const float* __restrict__ mb,
                        float* __restrict__ x1, __half* __restrict__ xn,
                        float* __restrict__ rm, float* __restrict__ rs)
{
    int r = blockIdx.x;
    long base = (long)r * DM;
    float v[3];
#pragma unroll
    for (int i = 0; i < 3; i++) {
        int c = threadIdx.x + i * 256;
        float bn = (__half2float(mo[base + c]) - cm[c]) * cs[c] * exg[c] + exb[c];
        v[i] = bn + x[base + c];
        x1[base + c] = v[i];
    }
    float s = v[0] + v[1] + v[2];
    float sq = v[0] * v[0] + v[1] * v[1] + v[2] * v[2];
    __shared__ float sh[256], sh2[256];
    sh[threadIdx.x] = s; sh2[threadIdx.x] = sq;
    __syncthreads();
    for (int st = 128; st > 0; st >>= 1) {
        if (threadIdx.x < st) { sh[threadIdx.x] += sh[threadIdx.x + st]; sh2[threadIdx.x] += sh2[threadIdx.x + st]; }
        __syncthreads();
    }
    float m = sh[0] / (float)DM;
    float rstd = rsqrtf(fmaxf(sh2[0] / (float)DM - m * m, 0.f) + EPSV);
    if (threadIdx.x == 0) { rm[r] = m; rs[r] = rstd; }
#pragma unroll
    for (int i = 0; i < 3; i++) {
        int c = threadIdx.x + i * 256;
        xn[base + c] = __float2half_rn((v[i] - m) * rstd * mg[c] + mb[c]);
    }
}

// fused x_final + LN stats
__global__ void xfinal_ln(const float* __restrict__ x1, const __half* __restrict__ mo,
                          const __half* __restrict__ gt, const float* __restrict__ x,
                          float* __restrict__ xf, float* __restrict__ rm,
                          float* __restrict__ rs)
{
    int r = blockIdx.x;
    long base = (long)r * DM;
    float v[3];
#pragma unroll
    for (int i = 0; i < 3; i++) {
        int c = threadIdx.x + i * 256;
        v[i] = x1[base + c] + __half2float(mo[base + c]) * __half2float(gt[base + c]) + x[base + c];
        xf[base + c] = v[i];
    }
    float s = v[0] + v[1] + v[2];
    float sq = v[0] * v[0] + v[1] * v[1] + v[2] * v[2];
    __shared__ float sh[256], sh2[256];
    sh[threadIdx.x] = s; sh2[threadIdx.x] = sq;
    __syncthreads();
    for (int st = 128; st > 0; st >>= 1) {
        if (threadIdx.x < st) { sh[threadIdx.x] += sh[threadIdx.x + st]; sh2[threadIdx.x] += sh2[threadIdx.x + st]; }
        __syncthreads();
    }
    if (threadIdx.x == 0) {
        float m = sh[0] / (float)DM;
        rm[r] = m;
        rs[r] = rsqrtf(fmaxf(sh2[0] / (float)DM - m * m, 0.f) + EPSV);
    }
}

__global__ void feat_attr_k(const float* __restrict__ x1, const float* __restrict__ rm,
                            const float* __restrict__ rs, const float* __restrict__ g,
                            const float* __restrict__ b, float* __restrict__ out)
{
    int d = blockIdx.x * 32 + threadIdx.x;
    int bb = blockIdx.y;
    float gd = g[d], bd = b[d];
    float best = -1e30f;
    for (int l = threadIdx.y; l < LQ; l += 8) {
        long row = (long)bb * LQ + l;
        float v = (x1[row * DM + d] - rm[row]) * rs[row] * gd + bd;
        best = fmaxf(best, v);
    }
    __shared__ float sh[8][33];
    sh[threadIdx.y][threadIdx.x] = best;
    __syncthreads();
    if (threadIdx.y == 0) {
#pragma unroll
        for (int i = 1; i < 8; i++) best = fmaxf(best, sh[i][threadIdx.x]);
        out[(long)bb * DM + d] = best;
    }
}

__global__ void feat_id_k(const float* __restrict__ xf, const float* __restrict__ rm,
                          const float* __restrict__ rs, const float* __restrict__ g,
                          const float* __restrict__ b, float* __restrict__ out)
{
    int d = blockIdx.x * 32 + threadIdx.x;
    int bb = blockIdx.y;
    float acc = 0.f;
    for (int l = threadIdx.y; l < LQ; l += 8) {
        long row = (long)bb * LQ + l;
        acc += (xf[row * DM + d] - rm[row]) * rs[row];
    }
    __shared__ float sh[8][33];
    sh[threadIdx.y][threadIdx.x] = acc;
    __syncthreads();
    if (threadIdx.y == 0) {
#pragma unroll
        for (int i = 1; i < 8; i++) acc += sh[i][threadIdx.x];
        out[(long)bb * DM + d] = (acc / (float)LQ) * g[d] + b[d];
    }
}

__global__ void idbn_k(const float* __restrict__ fid, const float* __restrict__ g,
                       const float* __restrict__ b, float* __restrict__ out)
{
    int d = blockIdx.x * blockDim.x + threadIdx.x;
    if (d >= DM) return;
    float s = 0.f;
    for (int bb = 0; bb < BSZ; bb++) s += fid[(long)bb * DM + d];
    float m = s / (float)BSZ;
    float vq = 0.f;
    for (int bb = 0; bb < BSZ; bb++) { float dv = fid[(long)bb * DM + d] - m; vq += dv * dv; }
    float rst = rsqrtf(vq / (float)BSZ + EPSV);
    for (int bb = 0; bb < BSZ; bb++)
        out[(long)bb * DM + d] = (fid[(long)bb * DM + d] - m) * rst * g[d] + b[d];
}

// ---------------- selective scan: 2 adjacent d per thread ------------------
__global__ void __launch_bounds__(128)
scan_k(const __half* __restrict__ xmc, const __half* __restrict__ del,
       const __half* __restrict__ dbc, const __half* __restrict__ z,
       const float* __restrict__ A_log, const float* __restrict__ Dp,
       __half* __restrict__ y)
{
    int b = blockIdx.y;
    int d = blockIdx.x * 256 + threadIdx.x * 2;
    float h0[DS], h1[DS];
    bool fast = true;
#pragma unroll
    for (int s = 0; s < DS; s++) {
        float a0 = -expf(A_log[(long)d * DS + s]);
        float a1 = -expf(A_log[(long)(d + 1) * DS + s]);
        h0[s] = 0.f; h1[s] = 0.f;
        float tol = 1e-4f * (float)(s + 1);
        fast = fast && (fabsf(a0 + (float)(s + 1)) < tol)
                    && (fabsf(a1 + (float)(s + 1)) < tol);
    }
    float Dp0 = Dp[d], Dp1 = Dp[d + 1];
    const long rb0 = (long)b * LQ;
    const __half* dbcb = dbc + rb0 * DXP + DTR;

    float2 dv = __half22float2(*(const __half2*)(del + rb0 * DI + d));
    float2 uv = __half22float2(*(const __half2*)(xmc + rb0 * DI + d));
    float2 zv = __half22float2(*(const __half2*)(z + rb0 * DI + d));
    uint4 bc[4];
#pragma unroll
    for (int i = 0; i < 4; i++) bc[i] = *(const uint4*)(dbcb + i * 8);

    for (int l = 0; l < LQ; l++) {
        // prefetch next row
        float2 dvn = make_float2(0.f, 0.f), uvn = dvn, zvn = dvn;
        uint4 bcn[4] = {};
        if (l + 1 < LQ) {
            long rb = rb0 + l + 1;
            dvn = __half22float2(*(const __half2*)(del + rb * DI + d));
            uvn = __half22float2(*(const __half2*)(xmc + rb * DI + d));
            zvn = __half22float2(*(const __half2*)(z + rb * DI + d));
            const __half* p = dbcb + (long)(l + 1) * DXP;
#pragma unroll
            for (int i = 0; i < 4; i++) bcn[i] = *(const uint4*)(p + i * 8);
        }

        const __half* bch = (const __half*)bc;
        float du0 = dv.x * uv.x, du1 = dv.y * uv.y;
        float y0 = 0.f, y1 = 0.f;
        if (fast) {
            float p0 = __expf(-dv.x), p1 = __expf(-dv.y);
            float e0 = 1.f, e1 = 1.f;
#pragma unroll
            for (int s = 0; s < DS; s++) {
                float Bs = __half2float(bch[s]);
                float Cs = __half2float(bch[DS + s]);
                e0 *= p0; e1 *= p1;
                h0[s] = h0[s] * e0 + du0 * Bs;
                h1[s] = h1[s] * e1 + du1 * Bs;
                y0 += h0[s] * Cs;
                y1 += h1[s] * Cs;
            }
        } else {
#pragma unroll
            for (int s = 0; s < DS; s++) {
                float Bs = __half2float(bch[s]);
                float Cs = __half2float(bch[DS + s]);
                float a0 = -__expf(A_log[(long)d * DS + s]);
                float a1 = -__expf(A_log[(long)(d + 1) * DS + s]);
                h0[s] = h0[s] * __expf(dv.x * a0) + du0 * Bs;
                h1[s] = h1[s] * __expf(dv.y * a1) + du1 * Bs;
                y0 += h0[s] * Cs;
                y1 += h1[s] * Cs;
            }
        }
        y0 += uv.x * Dp0;
        y1 += uv.y * Dp1;
        *(__half2*)(y + (rb0 + l) * DI + d) =
            __floats2half2_rn(y0 * fsilu(zv.x), y1 * fsilu(zv.y));

        dv = dvn; uv = uvn; zv = zvn;
#pragma unroll
        for (int i = 0; i < 4; i++) bc[i] = bcn[i];
    }
}

// ======================== host launcher ====================================
static inline dim3 tg_grid(int N) { return dim3((N + 127) / 128, ML / 128); }

extern "C" void kernel_launch(void* const* d_in, const int* in_sizes, int n_in,
                              void* d_out, int out_size)
{
    (void)in_sizes; (void)n_in; (void)out_size;
    const float* x         = (const float*)d_in[0];
    const float* sq_w      = (const float*)d_in[1];
    const float* sq_bn_g   = (const float*)d_in[2];
    const float* sq_bn_b   = (const float*)d_in[3];
    const float* dw_w      = (const float*)d_in[4];
    const float* dw_bn_g   = (const float*)d_in[5];
    const float* dw_bn_b   = (const float*)d_in[6];
    const float* ex_w      = (const float*)d_in[7];
    const float* ex_bn_g   = (const float*)d_in[8];
    const float* ex_bn_b   = (const float*)d_in[9];
    const float* attr_g    = (const float*)d_in[10];
    const float* attr_b    = (const float*)d_in[11];
    const float* mnorm_g   = (const float*)d_in[12];
    const float* mnorm_b   = (const float*)d_in[13];
    const float* in_proj_w = (const float*)d_in[14];
    const float* conv_w    = (const float*)d_in[15];
    const float* conv_b    = (const float*)d_in[16];
    const float* xproj_w   = (const float*)d_in[17];
    const float* dtproj_w  = (const float*)d_in[18];
    const float* dtproj_b  = (const float*)d_in[19];
    const float* A_log     = (const float*)d_in[20];
    const float* D_param   = (const float*)d_in[21];
    const float* out_proj_w= (const float*)d_in[22];
    const float* gate_w    = (const float*)d_in[23];
    const float* gate_b    = (const float*)d_in[24];
    const float* idn_g     = (const float*)d_in[25];
    const float* idn_b     = (const float*)d_in[26];
    const float* idbn_g    = (const float*)d_in[27];
    const float* idbn_b    = (const float*)d_in[28];
    float* out = (float*)d_out;

    __half *wh, *h, *h2, *xnh, *xm, *z, *xmc, *dbc, *del, *y, *mo, *gt;
    float *x1, *xf, *rm, *rs, *cm, *cs, *ps, *pq;
    cudaGetSymbolAddress((void**)&wh,  g_wh);
    cudaGetSymbolAddress((void**)&h,   g_h);
    cudaGetSymbolAddress((void**)&h2,  g_h2);
    cudaGetSymbolAddress((void**)&xnh, g_xnh);
    cudaGetSymbolAddress((void**)&xm,  g_xm);
    cudaGetSymbolAddress((void**)&z,   g_z);
    cudaGetSymbolAddress((void**)&xmc, g_xmc);
    cudaGetSymbolAddress((void**)&dbc, g_dbc);
    cudaGetSymbolAddress((void**)&del, g_del);
    cudaGetSymbolAddress((void**)&y,   g_y);
    cudaGetSymbolAddress((void**)&mo,  g_mo);
    cudaGetSymbolAddress((void**)&gt,  g_gt);
    cudaGetSymbolAddress((void**)&x1,  g_x1);
    cudaGetSymbolAddress((void**)&xf,  g_xf);
    cudaGetSymbolAddress((void**)&rm,  g_rm);
    cudaGetSymbolAddress((void**)&rs,  g_rs);
    cudaGetSymbolAddress((void**)&cm,  g_cm);
    cudaGetSymbolAddress((void**)&cs,  g_cs);
    cudaGetSymbolAddress((void**)&ps,  g_ps);
    cudaGetSymbolAddress((void**)&pq,  g_pq);

    cudaFuncSetAttribute(tgemm, cudaFuncAttributeMaxDynamicSharedMemorySize, TG_SMEMB);

    const long tD = (long)ML * DM;
    const long tH2 = (long)ML * NHID / 2;
    const long tI2 = (long)ML * DI / 2;

    // 0. convert all weights in one launch; x -> half
    wconv<<<(WH_TOT / 4 + 255) / 256, 256>>>(sq_w, ex_w, in_proj_w, gate_w,
                                             xproj_w, dtproj_w, out_proj_w, wh);
    f2h4<<<(int)((tD / 4 + 255) / 256), 256>>>(x, xnh, tD);

    // 1. squeeze proj + BN + silu
    tgemm<<<tg_grid(NHID), 256, TG_SMEMB>>>(xnh, DM, wh + OFF_SQ, DM, nullptr,
        h, NHID, nullptr, 0, 1 << 30, nullptr, 0, 1 << 30, nullptr, ML, NHID, DM, 0);
    bn_part<<<dim3(NHID / 32, BNCH), dim3(32, 32)>>>(h, ML, NHID, ps, pq);
    bn_final<<<1, NHID>>>(ps, pq, ML, NHID, cm, cs);
    bn_apply_h2<<<(int)((tH2 + 255) / 256), 256>>>(h, h, cm, cs, sq_bn_g, sq_bn_b, tH2, NHID);

    // 2. depthwise conv5 + BN + silu
    dwconv5_h2<<<(int)((tH2 + 255) / 256), 256>>>(h, dw_w, h2);
    bn_part<<<dim3(NHID / 32, BNCH), dim3(32, 32)>>>(h2, ML, NHID, ps, pq);
    bn_final<<<1, NHID>>>(ps, pq, ML, NHID, cm, cs);
    bn_apply_h2<<<(int)((tH2 + 255) / 256), 256>>>(h2, h2, cm, cs, dw_bn_g, dw_bn_b, tH2, NHID);

    // 3. expand proj -> mo; BN stats
    tgemm<<<tg_grid(DM), 256, TG_SMEMB>>>(h2, NHID, wh + OFF_EX, NHID, nullptr,
        mo, DM, nullptr, 0, 1 << 30, nullptr, 0, 1 << 30, nullptr, ML, DM, NHID, 0);
    bn_part<<<dim3(DM / 32, BNCH), dim3(32, 32)>>>(mo, ML, DM, ps, pq);
    bn_final<<<3, 256>>>(ps, pq, ML, DM, cm, cs);

    // 4/5. fused BN+resid -> x1, LN -> xn (+stats); feat_attr
    bnx1_ln<<<ML, 256>>>(mo, x, cm, cs, ex_bn_g, ex_bn_b, mnorm_g, mnorm_b, x1, xnh, rm, rs);
    feat_attr_k<<<dim3(DM / 32, BSZ), dim3(32, 8)>>>(x1, rm, rs, attr_g, attr_b, out);

    // 6+13. merged in_proj|gate -> xm | z | gt  (N = 2*DI + DM = 3840)
    tgemm<<<tg_grid(2 * DI + DM), 256, TG_SMEMB>>>(xnh, DM, wh + OFF_INP, DM, nullptr,
        xm, DI, z, DI, DI, gt, DM, 2 * DI, gate_b, ML, 2 * DI + DM, DM, 0);

    // 7. causal conv4 + bias + silu -> xmc
    cconv4_h2<<<(int)((tI2 + 255) / 256), 256>>>(xm, conv_w, conv_b, xmc);

    // 8. xproj -> dbc (dt | B | C)
    tgemm<<<tg_grid(DXP), 256, TG_SMEMB>>>(xmc, DI, wh + OFF_XP, DI, nullptr,
        dbc, DXP, nullptr, 0, 1 << 30, nullptr, 0, 1 << 30, nullptr, ML, DXP, DI, 0);

    // 9. dtproj + bias + softplus -> delta
    tgemm<<<tg_grid(DI), 256, TG_SMEMB>>>(dbc, DXP, wh + OFF_DT, DTR, dtproj_b,
        del, DI, nullptr, 0, 1 << 30, nullptr, 0, 1 << 30, nullptr, ML, DI, DTR, 2);

    // 10/11. selective scan -> y
    scan_k<<<dim3(DI / 256, BSZ), 128>>>(xmc, del, dbc, z, A_log, D_param, y);

    // 12. out_proj -> mamba_out
    tgemm<<<tg_grid(DM), 256, TG_SMEMB>>>(y, DI, wh + OFF_OP, DI, nullptr,
        mo, DM, nullptr, 0, 1 << 30, nullptr, 0, 1 << 30, nullptr, ML, DM, DI, 0);

    // 14/15. fused x_final + LN stats; feat_id
    xfinal_ln<<<ML, 256>>>(x1, mo, gt, x, xf, rm, rs);
    feat_id_k<<<dim3(DM / 32, BSZ), dim3(32, 8)>>>(xf, rm, rs, idn_g, idn_b, out + (long)BSZ * DM);

    // 16. BN over batch -> feat_id_bn
    idbn_k<<<DM / 256, 256>>>(out + (long)BSZ * DM, idbn_g, idbn_b, out + 2L * BSZ * DM);
}

// round 14
// speedup vs baseline: 1.0530x; 1.0530x over previous
#include <cuda_runtime.h>
#include <cuda_fp16.h>
#include <math.h>
#include <stdint.h>

#define BSZ   32
#define LQ    512
#define DM    768
#define NHID  192
#define KC    5
#define DI    1536
#define DS    16
#define DTR   48
#define DXP   (DTR+2*DS)      // 112
#define DCONV 4
#define ML    (BSZ*LQ)        // 16384 rows
#define EPSV  1e-5f
#define BNCH  32
#define SCCH  4               // scan chunks
#define SCL   (LQ/SCCH)       // 128 steps per chunk

// fp16-mma GEMM tiling: CTA 128x128, K-chunk 32 halfs, 8 warps 4x2
#define TGK     32
#define PITCHW  20
#define TILEW   (128*PITCHW)
#define TG_SMEMB (4*TILEW*4)            // 40960 bytes

// weight scratch offsets (halfs) — gate right after in_proj for merged GEMM
#define OFF_SQ  0
#define OFF_EX  147456
#define OFF_INP 294912
#define OFF_GW  2654208
#define OFF_XP  3244032
#define OFF_DT  3416064
#define OFF_OP  3489792
#define WH_TOT  4669440

// ---------------- scratch buffers ----------------
__device__ __half g_wh [WH_TOT];
__device__ __half g_h  [ML*NHID];
__device__ __half g_h2 [ML*NHID];
__device__ __half g_xnh[ML*DM];
__device__ __half g_xm [(size_t)ML*DI];
__device__ __half g_z  [(size_t)ML*DI];
__device__ __half g_xmc[(size_t)ML*DI];
__device__ __half g_dbc[ML*DXP];
__device__ __half g_del[(size_t)ML*DI];
__device__ __half g_y  [(size_t)ML*DI];
__device__ __half g_mo [ML*DM];
__device__ __half g_gt [ML*DM];
__device__ float  g_x1 [ML*DM];
__device__ float  g_xf [ML*DM];
__device__ float  g_rm [ML];
__device__ float  g_rs [ML];
__device__ float  g_cm [4096];
__device__ float  g_cs [4096];
__device__ float  g_ps [BNCH*1024];
__device__ float  g_pq [BNCH*1024];
__device__ float  g_hc [(size_t)BSZ*DI*SCCH*DS];   // chunk states (12.6MB)
__device__ float  g_hs [BSZ*DI*SCCH];              // chunk delta-sums

// ===================== helpers =============================================
__device__ __forceinline__ void mma_f16(float* d, const uint32_t* a, const uint32_t* b) {
    asm volatile(
        "mma.sync.aligned.m16n8k16.row.col.f32.f16.f16.f32 "
        "{%0,%1,%2,%3}, {%4,%5,%6,%7}, {%8,%9}, {%0,%1,%2,%3};"
        : "+f"(d[0]), "+f"(d[1]), "+f"(d[2]), "+f"(d[3])
        : "r"(a[0]), "r"(a[1]), "r"(a[2]), "r"(a[3]), "r"(b[0]), "r"(b[1]));
}
__device__ __forceinline__ void ldsm_x4(uint32_t& r0, uint32_t& r1, uint32_t& r2,
                                        uint32_t& r3, uint32_t addr) {
    asm volatile("ldmatrix.sync.aligned.m8n8.x4.shared.b16 {%0,%1,%2,%3}, [%4];"
                 : "=r"(r0), "=r"(r1), "=r"(r2), "=r"(r3) : "r"(addr));
}
__device__ __forceinline__ float fsilu(float v)   { return __fdividef(v, 1.f + __expf(-v)); }
__device__ __forceinline__ float fsigm(float v)   { return __fdividef(1.f, 1.f + __expf(-v)); }

// ---------------- converts -------------------------------------------------
__global__ void f2h4(const float* __restrict__ src, __half* __restrict__ dst, long n)
{
    long i = ((long)blockIdx.x * blockDim.x + threadIdx.x) * 4;
    if (i >= n) return;
    float4 v = *(const float4*)(src + i);
    *(__half2*)(dst + i)     = __floats2half2_rn(v.x, v.y);
    *(__half2*)(dst + i + 2) = __floats2half2_rn(v.z, v.w);
}
__global__ void wconv(const float* __restrict__ s0, const float* __restrict__ s1,
                      const float* __restrict__ s2, const float* __restrict__ s3,
                      const float* __restrict__ s4, const float* __restrict__ s5,
                      const float* __restrict__ s6, __half* __restrict__ dst)
{
    long i = ((long)blockIdx.x * blockDim.x + threadIdx.x) * 4;
    if (i >= WH_TOT) return;
    const float* src; long off;
    if      (i < OFF_EX)  { src = s0; off = i - OFF_SQ;  }
    else if (i < OFF_INP) { src = s1; off = i - OFF_EX;  }
    else if (i < OFF_GW)  { src = s2; off = i - OFF_INP; }
    else if (i < OFF_XP)  { src = s3; off = i - OFF_GW;  }
    else if (i < OFF_DT)  { src = s4; off = i - OFF_XP;  }
    else if (i < OFF_OP)  { src = s5; off = i - OFF_DT;  }
    else                  { src = s6; off = i - OFF_OP;  }
    float4 v = *(const float4*)(src + off);
    *(__half2*)(dst + i)     = __floats2half2_rn(v.x, v.y);
    *(__half2*)(dst + i + 2) = __floats2half2_rn(v.z, v.w);
}

// ===================== fp16 tensor GEMM (ldmatrix, 3-way split) ============
__global__ void __launch_bounds__(256, 2)
tgemm(const __half* __restrict__ A, int lda,
      const __half* __restrict__ W, int ldw,
      const float* __restrict__ bias,
      __half* __restrict__ C, int ldc,
      __half* __restrict__ C2, int ldc2, int splitN,
      __half* __restrict__ C3, int ldc3, int splitN2, const float* __restrict__ bias3,
      int M, int N, int K, int act)
{
    extern __shared__ uint32_t smem[];
    const int tid = threadIdx.x;
    const int wid = tid >> 5, lane = tid & 31;
    const int g = lane >> 2, t = lane & 3;
    const int wm = wid & 3, wn = wid >> 2;
    const int row0 = blockIdx.y * 128, col0 = blockIdx.x * 128;
    const uint32_t smem_b = (uint32_t)__cvta_generic_to_shared(smem);

    const int a_row = lane & 15;
    const int a_kw  = (lane >> 4) * 4;
    const int b_row = (lane & 7) + ((lane >> 4) << 3);
    const int b_kw  = ((lane >> 3) & 1) * 4;

    float acc[2][8][4];
#pragma unroll
    for (int mt = 0; mt < 2; mt++)
#pragma unroll
        for (int nt = 0; nt < 8; nt++)
#pragma unroll
            for (int j = 0; j < 4; j++) acc[mt][nt][j] = 0.f;

    const int nch = (K + TGK - 1) / TGK;

    uint4 pa[2], pb[2];
    auto ldg_chunk = [&](int ch) {
        const int k0 = ch * TGK;
#pragma unroll
        for (int i = 0; i < 2; i++) {
            int e = tid + i * 256;
            int r = e >> 2, q = e & 3;
            int gk = k0 + q * 8;
            pa[i] = make_uint4(0, 0, 0, 0);
            pb[i] = make_uint4(0, 0, 0, 0);
            if (gk < K) {
                pa[i] = *(const uint4*)(A + (long)(row0 + r) * lda + gk);
                int n = col0 + r;
                if (n < N) pb[i] = *(const uint4*)(W + (long)n * ldw + gk);
            }
        }
    };
    auto sts_chunk = [&](int buf) {
        uint32_t* As = smem + buf * 2 * TILEW;
        uint32_t* Bs = As + TILEW;
#pragma unroll
        for (int i = 0; i < 2; i++) {
            int e = tid + i * 256;
            int r = e >> 2, q = e & 3;
            int o = r * PITCHW + q * 4;
            *(uint4*)(As + o) = pa[i];
            *(uint4*)(Bs + o) = pb[i];
        }
    };
    auto compute_chunk = [&](int buf) {
        const uint32_t Ab = smem_b + (uint32_t)(buf * 2 * TILEW) * 4;
        const uint32_t Bb = Ab + TILEW * 4;
#pragma unroll
        for (int ks = 0; ks < 2; ks++) {
            const int kw = ks * 8;
            uint32_t af[2][4], bf[8][2];
#pragma unroll
            for (int mt = 0; mt < 2; mt++) {
                uint32_t addr = Ab + (uint32_t)(((wm * 32 + mt * 16 + a_row) * PITCHW
                                                + kw + a_kw) * 4);
                ldsm_x4(af[mt][0], af[mt][1], af[mt][2], af[mt][3], addr);
            }
#pragma unroll
            for (int j = 0; j < 4; j++) {
                uint32_t addr = Bb + (uint32_t)(((wn * 64 + j * 16 + b_row) * PITCHW
                                                + kw + b_kw) * 4);
                ldsm_x4(bf[2 * j][0], bf[2 * j][1], bf[2 * j + 1][0], bf[2 * j + 1][1], addr);
            }
#pragma unroll
            for (int mt = 0; mt < 2; mt++)
#pragma unroll
                for (int nt = 0; nt < 8; nt++)
                    mma_f16(acc[mt][nt], af[mt], bf[nt]);
        }
    };

    ldg_chunk(0);
    sts_chunk(0);
    __syncthreads();
    for (int ch = 1; ch < nch; ch++) {
        ldg_chunk(ch);
        compute_chunk((ch - 1) & 1);
        sts_chunk(ch & 1);
        __syncthreads();
    }
    compute_chunk((nch - 1) & 1);

    __half* Cp = C; int cof = col0, ldco = ldc;
    int actL = act; const float* bL = bias; int boff = 0;
    if (C3 && col0 >= splitN2) {
        Cp = C3; cof = col0 - splitN2; ldco = ldc3; actL = 3; bL = bias3; boff = splitN2;
    } else if (C2 && col0 >= splitN) {
        Cp = C2; cof = col0 - splitN; ldco = ldc2;
    }
#pragma unroll
    for (int mt = 0; mt < 2; mt++) {
        int r0 = row0 + wm * 32 + mt * 16 + g;
#pragma unroll
        for (int nt = 0; nt < 8; nt++) {
            int c0 = cof + wn * 64 + nt * 8 + t * 2;
            int cg = col0 + wn * 64 + nt * 8 + t * 2;
            if (cg >= N) continue;
#pragma unroll
            for (int half_ = 0; half_ < 2; half_++) {
                int r = r0 + half_ * 8;
                float v0 = acc[mt][nt][half_ * 2 + 0];
                float v1 = acc[mt][nt][half_ * 2 + 1];
                if (bL) { v0 += bL[cg - boff]; v1 += bL[cg - boff + 1]; }
                if (actL == 2) {
                    v0 = (v0 > 20.f) ? v0 : log1pf(__expf(v0));
                    v1 = (v1 > 20.f) ? v1 : log1pf(__expf(v1));
                } else if (actL == 3) {
                    v0 = fsigm(v0);
                    v1 = fsigm(v1);
                }
                *(__half2*)(Cp + (long)r * ldco + c0) = __floats2half2_rn(v0, v1);
            }
        }
    }
}

// ===================== two-phase BN stats ==================================
__global__ void bn_part(const __half* __restrict__ src, int M, int N,
                        float* __restrict__ ps, float* __restrict__ pq)
{
    int c = blockIdx.x * 32 + threadIdx.x;
    int ch = blockIdx.y;
    int rows = M / BNCH;
    int r0 = ch * rows;
    float s = 0.f, sq = 0.f;
    if (c < N) {
        for (int r = r0 + threadIdx.y; r < r0 + rows; r += blockDim.y) {
            float v = __half2float(src[(long)r * N + c]);
            s += v; sq += v * v;
        }
    }
    __shared__ float sh[32][33], sh2[32][33];
    sh[threadIdx.y][threadIdx.x] = s;
    sh2[threadIdx.y][threadIdx.x] = sq;
    __syncthreads();
    if (threadIdx.y == 0 && c < N) {
#pragma unroll
        for (int i = 1; i < 32; i++) { s += sh[i][threadIdx.x]; sq += sh2[i][threadIdx.x]; }
        ps[ch * N + c] = s;
        pq[ch * N + c] = sq;
    }
}
__global__ void bn_final(const float* __restrict__ ps, const float* __restrict__ pq,
                         int M, int N, float* __restrict__ mean, float* __restrict__ rstd)
{
    int c = blockIdx.x * blockDim.x + threadIdx.x;
    if (c >= N) return;
    float s = 0.f, sq = 0.f;
#pragma unroll
    for (int ch = 0; ch < BNCH; ch++) { s += ps[ch * N + c]; sq += pq[ch * N + c]; }
    float m = s / (float)M;
    mean[c] = m;
    rstd[c] = rsqrtf(fmaxf(sq / (float)M - m * m, 0.f) + EPSV);
}

__global__ void bn_apply_h2(const __half* __restrict__ src, __half* __restrict__ dst,
                            const float* __restrict__ mean, const float* __restrict__ rstd,
                            const float* __restrict__ g, const float* __restrict__ b,
                            long total2, int N)
{
    long i2 = (long)blockIdx.x * blockDim.x + threadIdx.x;
    if (i2 >= total2) return;
    long i = i2 * 2;
    int c = (int)(i % N);
    float2 f = __half22float2(*(const __half2*)(src + i));
    float v0 = (f.x - mean[c]) * rstd[c] * g[c] + b[c];
    float v1 = (f.y - mean[c + 1]) * rstd[c + 1] * g[c + 1] + b[c + 1];
    *(__half2*)(dst + i) = __floats2half2_rn(fsilu(v0), fsilu(v1));
}

__global__ void dwconv5_h2(const __half* __restrict__ src, const float* __restrict__ w,
                           __half* __restrict__ dst)
{
    long i2 = (long)blockIdx.x * blockDim.x + threadIdx.x;
    if (i2 >= (long)ML * NHID / 2) return;
    int c2 = (int)(i2 % (NHID / 2));
    int c = c2 * 2;
    long bl = i2 / (NHID / 2);
    int l = (int)(bl % LQ);
    long b = bl / LQ;
    float a0 = 0.f, a1 = 0.f;
#pragma unroll
    for (int k = 0; k < KC; k++) {
        int ll = l + k - 2;
        if (ll >= 0 && ll < LQ) {
            float2 f = __half22float2(*(const __half2*)(src + (b * LQ + ll) * NHID + c));
            a0 += f.x * w[c * KC + k];
            a1 += f.y * w[(c + 1) * KC + k];
        }
    }
    *(__half2*)(dst + bl * NHID + c) = __floats2half2_rn(a0, a1);
}

__global__ void cconv4_h2(const __half* __restrict__ xm, const float* __restrict__ w,
                          const float* __restrict__ cb, __half* __restrict__ dst)
{
    long i2 = (long)blockIdx.x * blockDim.x + threadIdx.x;
    if (i2 >= (long)ML * DI / 2) return;
    int c2 = (int)(i2 % (DI / 2));
    int c = c2 * 2;
    long bl = i2 / (DI / 2);
    int l = (int)(bl % LQ);
    long b = bl / LQ;
    float a0 = cb[c], a1 = cb[c + 1];
#pragma unroll
    for (int k = 0; k < DCONV; k++) {
        int ll = l + k - (DCONV - 1);
        if (ll >= 0) {
            float2 f = __half22float2(*(const __half2*)(xm + (b * LQ + ll) * (long)DI + c));
            a0 += f.x * w[c * DCONV + k];
            a1 += f.y * w[(c + 1) * DCONV + k];
        }
    }
    *(__half2*)(dst + bl * (long)DI + c) = __floats2half2_rn(fsilu(a0), fsilu(a1));
}

// fused BN(ex)+residual -> x1 ; LN stats ; LN apply -> xn (half)
__global__ void bnx1_ln(const __half* __restrict__ mo, const float* __restrict__ x,
                        const float* __restrict__ cm, const float* __restrict__ cs,
                        const float* __restrict__ exg, const float* __restrict__ exb,
                        const float* __restrict__ mg, const float* __restrict__ mb,
                        float* __restrict__ x1, __half* __restrict__ xn,
                        float* __restrict__ rm, float* __restrict__ rs)
{
    int r = blockIdx.x;
    long base = (long)r * DM;
    float v[3];
#pragma unroll
    for (int i = 0; i < 3; i++) {
        int c = threadIdx.x + i * 256;
        float bn = (__half2float(mo[base + c]) - cm[c]) * cs[c] * exg[c] + exb[c];
        v[i] = bn + x[base + c];
        x1[base + c] = v[i];
    }
    float s = v[0] + v[1] + v[2];
    float sq = v[0] * v[0] + v[1] * v[1] + v[2] * v[2];
    __shared__ float sh[256], sh2[256];
    sh[threadIdx.x] = s; sh2[threadIdx.x] = sq;
    __syncthreads();
    for (int st = 128; st > 0; st >>= 1) {
        if (threadIdx.x < st) { sh[threadIdx.x] += sh[threadIdx.x + st]; sh2[threadIdx.x] += sh2[threadIdx.x + st]; }
        __syncthreads();
    }
    float m = sh[0] / (float)DM;
    float rstd = rsqrtf(fmaxf(sh2[0] / (float)DM - m * m, 0.f) + EPSV);
    if (threadIdx.x == 0) { rm[r] = m; rs[r] = rstd; }
#pragma unroll
    for (int i = 0; i < 3; i++) {
        int c = threadIdx.x + i * 256;
        xn[base + c] = __float2half_rn((v[i] - m) * rstd * mg[c] + mb[c]);
    }
}

// fused x_final + LN stats
__global__ void xfinal_ln(const float* __restrict__ x1, const __half* __restrict__ mo,
                          const __half* __restrict__ gt, const float* __restrict__ x,
                          float* __restrict__ xf, float* __restrict__ rm,
                          float* __restrict__ rs)
{
    int r = blockIdx.x;
    long base = (long)r * DM;
    float v[3];
#pragma unroll
    for (int i = 0; i < 3; i++) {
        int c = threadIdx.x + i * 256;
        v[i] = x1[base + c] + __half2float(mo[base + c]) * __half2float(gt[base + c]) + x[base + c];
        xf[base + c] = v[i];
    }
    float s = v[0] + v[1] + v[2];
    float sq = v[0] * v[0] + v[1] * v[1] + v[2] * v[2];
    __shared__ float sh[256], sh2[256];
    sh[threadIdx.x] = s; sh2[threadIdx.x] = sq;
    __syncthreads();
    for (int st = 128; st > 0; st >>= 1) {
        if (threadIdx.x < st) { sh[threadIdx.x] += sh[threadIdx.x + st]; sh2[threadIdx.x] += sh2[threadIdx.x + st]; }
        __syncthreads();
    }
    if (threadIdx.x == 0) {
        float m = sh[0] / (float)DM;
        rm[r] = m;
        rs[r] = rsqrtf(fmaxf(sh2[0] / (float)DM - m * m, 0.f) + EPSV);
    }
}

__global__ void feat_attr_k(const float* __restrict__ x1, const float* __restrict__ rm,
                            const float* __restrict__ rs, const float* __restrict__ g,
                            const float* __restrict__ b, float* __restrict__ out)
{
    int d = blockIdx.x * 32 + threadIdx.x;
    int bb = blockIdx.y;
    float gd = g[d], bd = b[d];
    float best = -1e30f;
    for (int l = threadIdx.y; l < LQ; l += 8) {
        long row = (long)bb * LQ + l;
        float v = (x1[row * DM + d] - rm[row]) * rs[row] * gd + bd;
        best = fmaxf(best, v);
    }
    __shared__ float sh[8][33];
    sh[threadIdx.y][threadIdx.x] = best;
    __syncthreads();
    if (threadIdx.y == 0) {
#pragma unroll
        for (int i = 1; i < 8; i++) best = fmaxf(best, sh[i][threadIdx.x]);
        out[(long)bb * DM + d] = best;
    }
}

__global__ void feat_id_k(const float* __restrict__ xf, const float* __restrict__ rm,
                          const float* __restrict__ rs, const float* __restrict__ g,
                          const float* __restrict__ b, float* __restrict__ out)
{
    int d = blockIdx.x * 32 + threadIdx.x;
    int bb = blockIdx.y;
    float acc = 0.f;
    for (int l = threadIdx.y; l < LQ; l += 8) {
        long row = (long)bb * LQ + l;
        acc += (xf[row * DM + d] - rm[row]) * rs[row];
    }
    __shared__ float sh[8][33];
    sh[threadIdx.y][threadIdx.x] = acc;
    __syncthreads();
    if (threadIdx.y == 0) {
#pragma unroll
        for (int i = 1; i < 8; i++) acc += sh[i][threadIdx.x];
        out[(long)bb * DM + d] = (acc / (float)LQ) * g[d] + b[d];
    }
}

__global__ void idbn_k(const float* __restrict__ fid, const float* __restrict__ g,
                       const float* __restrict__ b, float* __restrict__ out)
{
    int d = blockIdx.x * blockDim.x + threadIdx.x;
    if (d >= DM) return;
    float s = 0.f;
    for (int bb = 0; bb < BSZ; bb++) s += fid[(long)bb * DM + d];
    float m = s / (float)BSZ;
    float vq = 0.f;
    for (int bb = 0; bb < BSZ; bb++) { float dv = fid[(long)bb * DM + d] - m; vq += dv * dv; }
    float rst = rsqrtf(vq / (float)BSZ + EPSV);
    for (int bb = 0; bb < BSZ; bb++)
        out[(long)bb * DM + d] = (fid[(long)bb * DM + d] - m) * rst * g[d] + b[d];
}

// ================= chunked-parallel selective scan =========================
// Pass 1: per (b,d,chunk c in 0..2): run recurrence from h=0, store h_loc + S
__global__ void __launch_bounds__(128)
scan_p1(const __half* __restrict__ xmc, const __half* __restrict__ del,
        const __half* __restrict__ dbc, const float* __restrict__ A_log,
        float* __restrict__ hc, float* __restrict__ hs)
{
    int b = blockIdx.y, c = blockIdx.z;
    int d = blockIdx.x * 128 + threadIdx.x;
    float A[DS], h[DS];
    bool fast = true;
#pragma unroll
    for (int s = 0; s < DS; s++) {
        A[s] = -expf(A_log[(long)d * DS + s]);
        h[s] = 0.f;
        fast = fast && (fabsf(A[s] + (float)(s + 1)) < 1e-4f * (float)(s + 1));
    }
    const long rb0 = (long)b * LQ + (long)c * SCL;
    float S = 0.f;
    for (int l = 0; l < SCL; l++) {
        long rb = rb0 + l;
        float dv = __half2float(del[rb * DI + d]);
        float uv = __half2float(xmc[rb * DI + d]);
        const __half* p = dbc + rb * DXP + DTR;
        uint4 bb[2];
        bb[0] = *(const uint4*)p;
        bb[1] = *(const uint4*)(p + 8);
        const __half* Bh = (const __half*)bb;
        S += dv;
        float du = dv * uv;
        if (fast) {
            float pp = __expf(-dv), e = 1.f;
#pragma unroll
            for (int s = 0; s < DS; s++) {
                e *= pp;
                h[s] = h[s] * e + du * __half2float(Bh[s]);
            }
        } else {
#pragma unroll
            for (int s = 0; s < DS; s++)
                h[s] = h[s] * __expf(dv * A[s]) + du * __half2float(Bh[s]);
        }
    }
    long o = ((long)b * DI + d) * SCCH + c;
    hs[o] = S;
#pragma unroll
    for (int s = 0; s < DS; s++) hc[o * DS + s] = h[s];
}

// Pass 2: combine chunk transfers -> h_in per chunk (slot c gets initial state)
__global__ void scan_p2(const float* __restrict__ A_log, float* __restrict__ hc,
                        const float* __restrict__ hs)
{
    int idx = blockIdx.x * 256 + threadIdx.x;
    if (idx >= BSZ * DI) return;
    int d = idx % DI;
    float A[DS];
    bool fast = true;
#pragma unroll
    for (int s = 0; s < DS; s++) {
        A[s] = -expf(A_log[(long)d * DS + s]);
        fast = fast && (fabsf(A[s] + (float)(s + 1)) < 1e-4f * (float)(s + 1));
    }
    long base = (long)idx * SCCH;
    float S1 = hs[base + 1], S2 = hs[base + 2];
    float h0[DS], h1[DS], h2[DS];
#pragma unroll
    for (int s = 0; s < DS; s++) {
        h0[s] = hc[(base + 0) * DS + s];
        h1[s] = hc[(base + 1) * DS + s];
        h2[s] = hc[(base + 2) * DS + s];
    }
    float hi[DS];
#pragma unroll
    for (int s = 0; s < DS; s++) { hi[s] = h0[s]; hc[(base + 1) * DS + s] = hi[s]; }
    if (fast) {
        float p = __expf(-S1), e = 1.f;
#pragma unroll
        for (int s = 0; s < DS; s++) { e *= p; hi[s] = hi[s] * e + h1[s]; }
    } else {
#pragma unroll
        for (int s = 0; s < DS; s++) hi[s] = hi[s] * __expf(A[s] * S1) + h1[s];
    }
#pragma unroll
    for (int s = 0; s < DS; s++) hc[(base + 2) * DS + s] = hi[s];
    if (fast) {
        float p = __expf(-S2), e = 1.f;
#pragma unroll
        for (int s = 0; s < DS; s++) { e *= p; hi[s] = hi[s] * e + h2[s]; }
    } else {
#pragma unroll
        for (int s = 0; s < DS; s++) hi[s] = hi[s] * __expf(A[s] * S2) + h2[s];
    }
#pragma unroll
    for (int s = 0; s < DS; s++) hc[(base + 3) * DS + s] = hi[s];
#pragma unroll
    for (int s = 0; s < DS; s++) hc[(base + 0) * DS + s] = 0.f;
}

// Pass 3: per (b,d,chunk): rerun from true h_in, write y
__global__ void __launch_bounds__(128)
scan_p3(const __half* __restrict__ xmc, const __half* __restrict__ del,
        const __half* __restrict__ dbc, const __half* __restrict__ z,
        const float* __restrict__ A_log, const float* __restrict__ Dp,
        const float* __restrict__ hc, __half* __restrict__ y)
{
    int b = blockIdx.y, c = blockIdx.z;
    int d = blockIdx.x * 128 + threadIdx.x;
    float A[DS], h[DS];
    bool fast = true;
#pragma unroll
    for (int s = 0; s < DS; s++) {
        A[s] = -expf(A_log[(long)d * DS + s]);
        fast = fast && (fabsf(A[s] + (float)(s + 1)) < 1e-4f * (float)(s + 1));
    }
    long o = ((long)b * DI + d) * SCCH + c;
#pragma unroll
    for (int s = 0; s < DS; s++) h[s] = hc[o * DS + s];
    float Dpv = Dp[d];
    const long rb0 = (long)b * LQ + (long)c * SCL;
    for (int l = 0; l < SCL; l++) {
        long rb = rb0 + l;
        float dv = __half2float(del[rb * DI + d]);
        float uv = __half2float(xmc[rb * DI + d]);
        float zv = __half2float(z[rb * DI + d]);
        const __half* p = dbc + rb * DXP + DTR;
        uint4 bb[4];
        bb[0] = *(const uint4*)p;
        bb[1] = *(const uint4*)(p + 8);
        bb[2] = *(const uint4*)(p + 16);
        bb[3] = *(const uint4*)(p + 24);
        const __half* Bh = (const __half*)bb;
        float du = dv * uv;
        float yv = 0.f;
        if (fast) {
            float pp = __expf(-dv), e = 1.f;
#pragma unroll
            for (int s = 0; s < DS; s++) {
                e *= pp;
                h[s] = h[s] * e + du * __half2float(Bh[s]);
                yv += h[s] * __half2float(Bh[DS + s]);
            }
        } else {
#pragma unroll
            for (int s = 0; s < DS; s++) {
                h[s] = h[s] * __expf(dv * A[s]) + du * __half2float(Bh[s]);
                yv += h[s] * __half2float(Bh[DS + s]);
            }
        }
        yv += uv * Dpv;
        y[rb * DI + d] = __float2half_rn(yv * fsilu(zv));
    }
}

// ======================== host launcher ====================================
static inline dim3 tg_grid(int N) { return dim3((N + 127) / 128, ML / 128); }

extern "C" void kernel_launch(void* const* d_in, const int* in_sizes, int n_in,
                              void* d_out, int out_size)
{
    (void)in_sizes; (void)n_in; (void)out_size;
    const float* x         = (const float*)d_in[0];
    const float* sq_w      = (const float*)d_in[1];
    const float* sq_bn_g   = (const float*)d_in[2];
    const float* sq_bn_b   = (const float*)d_in[3];
    const float* dw_w      = (const float*)d_in[4];
    const float* dw_bn_g   = (const float*)d_in[5];
    const float* dw_bn_b   = (const float*)d_in[6];
    const float* ex_w      = (const float*)d_in[7];
    const float* ex_bn_g   = (const float*)d_in[8];
    const float* ex_bn_b   = (const float*)d_in[9];
    const float* attr_g    = (const float*)d_in[10];
    const float* attr_b    = (const float*)d_in[11];
    const float* mnorm_g   = (const float*)d_in[12];
    const float* mnorm_b   = (const float*)d_in[13];
    const float* in_proj_w = (const float*)d_in[14];
    const float* conv_w    = (const float*)d_in[15];
    const float* conv_b    = (const float*)d_in[16];
    const float* xproj_w   = (const float*)d_in[17];
    const float* dtproj_w  = (const float*)d_in[18];
    const float* dtproj_b  = (const float*)d_in[19];
    const float* A_log     = (const float*)d_in[20];
    const float* D_param   = (const float*)d_in[21];
    const float* out_proj_w= (const float*)d_in[22];
    const float* gate_w    = (const float*)d_in[23];
    const float* gate_b    = (const float*)d_in[24];
    const float* idn_g     = (const float*)d_in[25];
    const float* idn_b     = (const float*)d_in[26];
    const float* idbn_g    = (const float*)d_in[27];
    const float* idbn_b    = (const float*)d_in[28];
    float* out = (float*)d_out;

    __half *wh, *h, *h2, *xnh, *xm, *z, *xmc, *dbc, *del, *y, *mo, *gt;
    float *x1, *xf, *rm, *rs, *cm, *cs, *ps, *pq, *hc, *hs;
    cudaGetSymbolAddress((void**)&wh,  g_wh);
    cudaGetSymbolAddress((void**)&h,   g_h);
    cudaGetSymbolAddress((void**)&h2,  g_h2);
    cudaGetSymbolAddress((void**)&xnh, g_xnh);
    cudaGetSymbolAddress((void**)&xm,  g_xm);
    cudaGetSymbolAddress((void**)&z,   g_z);
    cudaGetSymbolAddress((void**)&xmc, g_xmc);
    cudaGetSymbolAddress((void**)&dbc, g_dbc);
    cudaGetSymbolAddress((void**)&del, g_del);
    cudaGetSymbolAddress((void**)&y,   g_y);
    cudaGetSymbolAddress((void**)&mo,  g_mo);
    cudaGetSymbolAddress((void**)&gt,  g_gt);
    cudaGetSymbolAddress((void**)&x1,  g_x1);
    cudaGetSymbolAddress((void**)&xf,  g_xf);
    cudaGetSymbolAddress((void**)&rm,  g_rm);
    cudaGetSymbolAddress((void**)&rs,  g_rs);
    cudaGetSymbolAddress((void**)&cm,  g_cm);
    cudaGetSymbolAddress((void**)&cs,  g_cs);
    cudaGetSymbolAddress((void**)&ps,  g_ps);
    cudaGetSymbolAddress((void**)&pq,  g_pq);
    cudaGetSymbolAddress((void**)&hc,  g_hc);
    cudaGetSymbolAddress((void**)&hs,  g_hs);

    cudaFuncSetAttribute(tgemm, cudaFuncAttributeMaxDynamicSharedMemorySize, TG_SMEMB);

    const long tD = (long)ML * DM;
    const long tH2 = (long)ML * NHID / 2;
    const long tI2 = (long)ML * DI / 2;

    // 0. convert all weights in one launch; x -> half
    wconv<<<(WH_TOT / 4 + 255) / 256, 256>>>(sq_w, ex_w, in_proj_w, gate_w,
                                             xproj_w, dtproj_w, out_proj_w, wh);
    f2h4<<<(int)((tD / 4 + 255) / 256), 256>>>(x, xnh, tD);

    // 1. squeeze proj + BN + silu
    tgemm<<<tg_grid(NHID), 256, TG_SMEMB>>>(xnh, DM, wh + OFF_SQ, DM, nullptr,
        h, NHID, nullptr, 0, 1 << 30, nullptr, 0, 1 << 30, nullptr, ML, NHID, DM, 0);
    bn_part<<<dim3(NHID / 32, BNCH), dim3(32, 32)>>>(h, ML, NHID, ps, pq);
    bn_final<<<1, NHID>>>(ps, pq, ML, NHID, cm, cs);
    bn_apply_h2<<<(int)((tH2 + 255) / 256), 256>>>(h, h, cm, cs, sq_bn_g, sq_bn_b, tH2, NHID);

    // 2. depthwise conv5 + BN + silu
    dwconv5_h2<<<(int)((tH2 + 255) / 256), 256>>>(h, dw_w, h2);
    bn_part<<<dim3(NHID / 32, BNCH), dim3(32, 32)>>>(h2, ML, NHID, ps, pq);
    bn_final<<<1, NHID>>>(ps, pq, ML, NHID, cm, cs);
    bn_apply_h2<<<(int)((tH2 + 255) / 256), 256>>>(h2, h2, cm, cs, dw_bn_g, dw_bn_b, tH2, NHID);

    // 3. expand proj -> mo; BN stats
    tgemm<<<tg_grid(DM), 256, TG_SMEMB>>>(h2, NHID, wh + OFF_EX, NHID, nullptr,
        mo, DM, nullptr, 0, 1 << 30, nullptr, 0, 1 << 30, nullptr, ML, DM, NHID, 0);
    bn_part<<<dim3(DM / 32, BNCH), dim3(32, 32)>>>(mo, ML, DM, ps, pq);
    bn_final<<<3, 256>>>(ps, pq, ML, DM, cm, cs);

    // 4/5. fused BN+resid -> x1, LN -> xn (+stats); feat_attr
    bnx1_ln<<<ML, 256>>>(mo, x, cm, cs, ex_bn_g, ex_bn_b, mnorm_g, mnorm_b, x1, xnh, rm, rs);
    feat_attr_k<<<dim3(DM / 32, BSZ), dim3(32, 8)>>>(x1, rm, rs, attr_g, attr_b, out);

    // 6+13. merged in_proj|gate -> xm | z | gt  (N = 2*DI + DM = 3840)
    tgemm<<<tg_grid(2 * DI + DM), 256, TG_SMEMB>>>(xnh, DM, wh + OFF_INP, DM, nullptr,
        xm, DI, z, DI, DI, gt, DM, 2 * DI, gate_b, ML, 2 * DI + DM, DM, 0);

    // 7. causal conv4 + bias + silu -> xmc
    cconv4_h2<<<(int)((tI2 + 255) / 256), 256>>>(xm, conv_w, conv_b, xmc);

    // 8. xproj -> dbc (dt | B | C)
    tgemm<<<tg_grid(DXP), 256, TG_SMEMB>>>(xmc, DI, wh + OFF_XP, DI, nullptr,
        dbc, DXP, nullptr, 0, 1 << 30, nullptr, 0, 1 << 30, nullptr, ML, DXP, DI, 0);

    // 9. dtproj + bias + softplus -> delta
    tgemm<<<tg_grid(DI), 256, TG_SMEMB>>>(dbc, DXP, wh + OFF_DT, DTR, dtproj_b,
        del, DI, nullptr, 0, 1 << 30, nullptr, 0, 1 << 30, nullptr, ML, DI, DTR, 2);

    // 10/11. chunked-parallel selective scan -> y
    scan_p1<<<dim3(DI / 128, BSZ, SCCH - 1), 128>>>(xmc, del, dbc, A_log, hc, hs);
    scan_p2<<<(BSZ * DI + 255) / 256, 256>>>(A_log, hc, hs);
    scan_p3<<<dim3(DI / 128, BSZ, SCCH), 128>>>(xmc, del, dbc, z, A_log, D_param, hc, y);

    // 12. out_proj -> mamba_out
    tgemm<<<tg_grid(DM), 256, TG_SMEMB>>>(y, DI, wh + OFF_OP, DI, nullptr,
        mo, DM, nullptr, 0, 1 << 30, nullptr, 0, 1 << 30, nullptr, ML, DM, DI, 0);

    // 14/15. fused x_final + LN stats; feat_id
    xfinal_ln<<<ML, 256>>>(x1, mo, gt, x, xf, rm, rs);
    feat_id_k<<<dim3(DM / 32, BSZ), dim3(32, 8)>>>(xf, rm, rs, idn_g, idn_b, out + (long)BSZ * DM);

    // 16. BN over batch -> feat_id_bn
    idbn_k<<<DM / 256, 256>>>(out + (long)BSZ * DM, idbn_g, idbn_b, out + 2L * BSZ * DM);
}